// round 11
// baseline (speedup 1.0000x reference)
#include <cuda_runtime.h>
#include <cuda_fp16.h>
#include <cstdint>

#define NHALF 4096
#define TN    8192
#define D     128
#define BM    128
#define NB    (TN / BM)                 // 64
#define NTILES (NB * (NB + 1) / 2)      // 2080 lower-triangle tiles
#define PITCH 136                        // smem pitch in fp16 elems (conflict-free)

__device__ __half g_pnh[(size_t)TN * D];   // fp16 normalized rows
__device__ float  g_rowsum[TN];            // sum_{j != i} exp(sim_ij)

// ---------------------------------------------------------------------------
// 1) Normalize: 4 rows per warp (MLP=4), fp16 output; zero rowsums + out.
// ---------------------------------------------------------------------------
__global__ void normalize_kernel(const float* __restrict__ zi,
                                 const float* __restrict__ zj,
                                 float* __restrict__ out) {
    int warp = (blockIdx.x * blockDim.x + threadIdx.x) >> 5;   // 0..2047
    int lane = threadIdx.x & 31;
    if (blockIdx.x == 0 && threadIdx.x == 0) *out = 0.0f;
    int row0 = warp * 4;
    if (row0 >= TN) return;

    float4 v[4];
#pragma unroll
    for (int r = 0; r < 4; r++) {
        int row = row0 + r;
        const float* src = (row < NHALF) ? (zi + (size_t)row * D)
                                         : (zj + (size_t)(row - NHALF) * D);
        v[r] = ((const float4*)src)[lane];
    }
#pragma unroll
    for (int r = 0; r < 4; r++) {
        float ss = v[r].x * v[r].x + v[r].y * v[r].y + v[r].z * v[r].z + v[r].w * v[r].w;
#pragma unroll
        for (int o = 16; o > 0; o >>= 1) ss += __shfl_xor_sync(0xffffffffu, ss, o);
        float inv = 1.0f / fmaxf(sqrtf(ss), 1e-8f);
        int row = row0 + r;
        __half2 h0 = __floats2half2_rn(v[r].x * inv, v[r].y * inv);
        __half2 h1 = __floats2half2_rn(v[r].z * inv, v[r].w * inv);
        uint2 u;
        u.x = *reinterpret_cast<uint32_t*>(&h0);
        u.y = *reinterpret_cast<uint32_t*>(&h1);
        ((uint2*)(g_pnh + (size_t)row * D))[lane] = u;
        if (lane == 0) g_rowsum[row] = 0.0f;
    }
}

// ---------------------------------------------------------------------------
// 2) Fused fp16 HMMA (fp16 accum) sim-GEMM + exp + row/col sums.
//    256 threads = 8 warps (2x4), warp tile 64x32, mma.sync m16n8k16 f16.f16.
// ---------------------------------------------------------------------------
__device__ __forceinline__ void ldsm4(uint32_t& r0, uint32_t& r1,
                                      uint32_t& r2, uint32_t& r3, uint32_t addr) {
    asm volatile("ldmatrix.sync.aligned.m8n8.x4.shared.b16 {%0,%1,%2,%3}, [%4];"
                 : "=r"(r0), "=r"(r1), "=r"(r2), "=r"(r3) : "r"(addr));
}
__device__ __forceinline__ void mma16816h(uint32_t* d, const uint32_t* a, const uint32_t* b) {
    asm volatile(
        "mma.sync.aligned.m16n8k16.row.col.f16.f16.f16.f16 "
        "{%0,%1}, {%2,%3,%4,%5}, {%6,%7}, {%0,%1};"
        : "+r"(d[0]), "+r"(d[1])
        : "r"(a[0]), "r"(a[1]), "r"(a[2]), "r"(a[3]), "r"(b[0]), "r"(b[1]));
}

__global__ __launch_bounds__(256, 2) void simgemm_kernel() {
    // triangular decode: bid -> (by, bx <= by)
    int bid = blockIdx.x;
    int by = (int)((sqrtf(8.0f * (float)bid + 1.0f) - 1.0f) * 0.5f);
    while ((by + 1) * (by + 2) / 2 <= bid) by++;
    while (by * (by + 1) / 2 > bid) by--;
    int bx = bid - by * (by + 1) / 2;
    bool diag = (bx == by);

    extern __shared__ char smem_raw[];
    __half* As = (__half*)smem_raw;                          // [128][PITCH]
    __half* Bs = As + BM * PITCH;                            // [128][PITCH]
    float* rsum = (float*)(Bs + BM * PITCH);                 // [128]
    float* csum = rsum + BM;                                 // [128]

    int tid = threadIdx.x, lane = tid & 31, wid = tid >> 5;

    // ---- load tiles, coalesced uint4; diag reuses As as Bs
    const __half* srcA = g_pnh + (size_t)by * BM * D;
    const __half* srcB = g_pnh + (size_t)bx * BM * D;
#pragma unroll
    for (int it = 0; it < (BM * D) / (256 * 8); it++) {
        int e = it * 2048 + tid * 8;
        int row = e >> 7, col = e & 127;
        *(uint4*)&As[row * PITCH + col] = *(const uint4*)&srcA[e];
        if (!diag) *(uint4*)&Bs[row * PITCH + col] = *(const uint4*)&srcB[e];
    }
    if (tid < BM) { rsum[tid] = 0.0f; csum[tid] = 0.0f; }
    __syncthreads();

    // ---- warp tiling: 2 (M) x 4 (N) warps; warp tile 64x32
    int wm = (wid >> 2) * 64;
    int wn = (wid & 3) * 32;
    uint32_t aTile = (uint32_t)__cvta_generic_to_shared(As);
    uint32_t bTile = diag ? aTile : (uint32_t)__cvta_generic_to_shared(Bs);

    uint32_t acc[4][4][2];
#pragma unroll
    for (int mt = 0; mt < 4; mt++)
#pragma unroll
        for (int nt = 0; nt < 4; nt++) { acc[mt][nt][0] = 0u; acc[mt][nt][1] = 0u; }

#pragma unroll
    for (int ks = 0; ks < 8; ks++) {
        int k0 = ks * 16;
        uint32_t a[4][4], b[4][2];
#pragma unroll
        for (int mt = 0; mt < 4; mt++) {
            int row = wm + mt * 16 + (lane & 15);
            int col = k0 + ((lane >> 4) << 3);
            ldsm4(a[mt][0], a[mt][1], a[mt][2], a[mt][3],
                  aTile + (uint32_t)(row * PITCH + col) * 2u);
        }
#pragma unroll
        for (int np = 0; np < 2; np++) {
            int g = lane >> 3;
            int row = wn + np * 16 + ((g >> 1) << 3) + (lane & 7);
            int col = k0 + ((g & 1) << 3);
            uint32_t r0, r1, r2, r3;
            ldsm4(r0, r1, r2, r3, bTile + (uint32_t)(row * PITCH + col) * 2u);
            b[np * 2 + 0][0] = r0; b[np * 2 + 0][1] = r1;
            b[np * 2 + 1][0] = r2; b[np * 2 + 1][1] = r3;
        }
#pragma unroll
        for (int mt = 0; mt < 4; mt++)
#pragma unroll
            for (int nt = 0; nt < 4; nt++)
                mma16816h(acc[mt][nt], a[mt], b[nt]);
    }

    // ---- epilogue: unpack fp16 pairs -> fp32, exp (sim <= 2), diag masked
    int r0 = lane >> 2, c0 = (lane & 3) * 2;
    float rp[8], cp[8];
#pragma unroll
    for (int i = 0; i < 8; i++) { rp[i] = 0.0f; cp[i] = 0.0f; }

#pragma unroll
    for (int mt = 0; mt < 4; mt++) {
#pragma unroll
        for (int nt = 0; nt < 4; nt++) {
            float2 p0 = __half22float2(*reinterpret_cast<__half2*>(&acc[mt][nt][0]));
            float2 p1 = __half22float2(*reinterpret_cast<__half2*>(&acc[mt][nt][1]));
            float e0 = __expf(p0.x * 2.0f);
            float e1 = __expf(p0.y * 2.0f);
            float e2 = __expf(p1.x * 2.0f);
            float e3 = __expf(p1.y * 2.0f);
            if (diag) {
                int lr = wm + mt * 16 + r0;
                int lc = wn + nt * 8 + c0;
                if (lr == lc)         e0 = 0.0f;
                if (lr == lc + 1)     e1 = 0.0f;
                if (lr + 8 == lc)     e2 = 0.0f;
                if (lr + 8 == lc + 1) e3 = 0.0f;
            }
            rp[mt * 2 + 0] += e0 + e1;
            rp[mt * 2 + 1] += e2 + e3;
            cp[nt * 2 + 0] += e0 + e2;
            cp[nt * 2 + 1] += e1 + e3;
        }
    }

#pragma unroll
    for (int o = 1; o <= 2; o <<= 1)
#pragma unroll
        for (int i = 0; i < 8; i++) rp[i] += __shfl_xor_sync(0xffffffffu, rp[i], o);
    if ((lane & 3) == 0) {
#pragma unroll
        for (int mt = 0; mt < 4; mt++) {
            atomicAdd(&rsum[wm + mt * 16 + r0 + 0], rp[mt * 2 + 0]);
            atomicAdd(&rsum[wm + mt * 16 + r0 + 8], rp[mt * 2 + 1]);
        }
    }
#pragma unroll
    for (int o = 4; o <= 16; o <<= 1)
#pragma unroll
        for (int i = 0; i < 8; i++) cp[i] += __shfl_xor_sync(0xffffffffu, cp[i], o);
    if (lane < 4) {
#pragma unroll
        for (int nt = 0; nt < 4; nt++) {
            atomicAdd(&csum[wn + nt * 8 + lane * 2 + 0], cp[nt * 2 + 0]);
            atomicAdd(&csum[wn + nt * 8 + lane * 2 + 1], cp[nt * 2 + 1]);
        }
    }
    __syncthreads();

    if (tid < BM) {
        atomicAdd(&g_rowsum[by * BM + tid], rsum[tid]);
    } else if (!diag) {
        atomicAdd(&g_rowsum[bx * BM + (tid - BM)], csum[tid - BM]);
    }
}

// ---------------------------------------------------------------------------
// 3) Finalize: 4 rows per warp; pos from fp16 rows (fp32 accumulate);
//    block reduction, 1 global atomic per block.
// ---------------------------------------------------------------------------
__global__ void finalize_kernel(float* __restrict__ out) {
    __shared__ float bred[8];
    int warp = (blockIdx.x * blockDim.x + threadIdx.x) >> 5;  // 0..2047
    int lane = threadIdx.x & 31, wib = (threadIdx.x >> 5);
    int row0 = warp * 4;

    float local = 0.0f;
    if (row0 < TN) {
        uint2 v[4], w[4];
#pragma unroll
        for (int r = 0; r < 4; r++) {
            int row = row0 + r;
            int pair = (row < NHALF) ? row + NHALF : row - NHALF;
            v[r] = ((const uint2*)(g_pnh + (size_t)row * D))[lane];
            w[r] = ((const uint2*)(g_pnh + (size_t)pair * D))[lane];
        }
#pragma unroll
        for (int r = 0; r < 4; r++) {
            float2 v0 = __half22float2(*reinterpret_cast<__half2*>(&v[r].x));
            float2 v1 = __half22float2(*reinterpret_cast<__half2*>(&v[r].y));
            float2 w0 = __half22float2(*reinterpret_cast<__half2*>(&w[r].x));
            float2 w1 = __half22float2(*reinterpret_cast<__half2*>(&w[r].y));
            float pd = v0.x * w0.x + v0.y * w0.y + v1.x * w1.x + v1.y * w1.y;
#pragma unroll
            for (int o = 16; o > 0; o >>= 1) pd += __shfl_xor_sync(0xffffffffu, pd, o);
            if (lane == 0)
                local += logf(g_rowsum[row0 + r]) - pd * 2.0f;
        }
    }
    if (lane == 0) bred[wib] = local;
    __syncthreads();
    if (threadIdx.x == 0) {
        float s = 0.0f;
#pragma unroll
        for (int i = 0; i < 8; i++) s += bred[i];
        atomicAdd(out, s * (1.0f / (float)TN));
    }
}

// ---------------------------------------------------------------------------
extern "C" void kernel_launch(void* const* d_in, const int* in_sizes, int n_in,
                              void* d_out, int out_size) {
    const float* zi = (const float*)d_in[0];
    const float* zj = (const float*)d_in[1];
    float* out = (float*)d_out;

    normalize_kernel<<<TN / 32, 256>>>(zi, zj, out);   // also zeros *out

    size_t smem_bytes = (size_t)(2 * BM * PITCH) * sizeof(__half)
                        + 2 * BM * sizeof(float);
    static bool attr_set = false;
    if (!attr_set) {
        cudaFuncSetAttribute(simgemm_kernel,
                             cudaFuncAttributeMaxDynamicSharedMemorySize,
                             (int)smem_bytes);
        attr_set = true;
    }
    simgemm_kernel<<<NTILES, 256, smem_bytes>>>();

    finalize_kernel<<<TN / 32, 256>>>(out);
}

// round 16
// speedup vs baseline: 1.1420x; 1.1420x over previous
#include <cuda_runtime.h>
#include <cuda_fp16.h>
#include <cstdint>

#define NHALF 4096
#define TN    8192
#define D     128
#define BM    128
#define NB    (TN / BM)                 // 64
#define NTILES (NB * (NB + 1) / 2)      // 2080 lower-triangle tiles
#define PITCH 136                        // smem pitch in fp16 elems (conflict-free)

__device__ __half g_pnh[(size_t)TN * D];   // fp16 normalized rows
__device__ float  g_rowsum[TN];            // sum_{j != i} exp(sim_ij)

// ---------------------------------------------------------------------------
// 1) Normalize: 2 rows per warp, grid 512 (more blocks for latency hiding).
// ---------------------------------------------------------------------------
__global__ void normalize_kernel(const float* __restrict__ zi,
                                 const float* __restrict__ zj,
                                 float* __restrict__ out) {
    int warp = (blockIdx.x * blockDim.x + threadIdx.x) >> 5;   // 0..4095
    int lane = threadIdx.x & 31;
    if (blockIdx.x == 0 && threadIdx.x == 0) *out = 0.0f;
    int row0 = warp * 2;
    if (row0 >= TN) return;

    float4 v[2];
#pragma unroll
    for (int r = 0; r < 2; r++) {
        int row = row0 + r;
        const float* src = (row < NHALF) ? (zi + (size_t)row * D)
                                         : (zj + (size_t)(row - NHALF) * D);
        v[r] = ((const float4*)src)[lane];
    }
#pragma unroll
    for (int r = 0; r < 2; r++) {
        float ss = v[r].x * v[r].x + v[r].y * v[r].y + v[r].z * v[r].z + v[r].w * v[r].w;
#pragma unroll
        for (int o = 16; o > 0; o >>= 1) ss += __shfl_xor_sync(0xffffffffu, ss, o);
        float inv = 1.0f / fmaxf(sqrtf(ss), 1e-8f);
        int row = row0 + r;
        __half2 h0 = __floats2half2_rn(v[r].x * inv, v[r].y * inv);
        __half2 h1 = __floats2half2_rn(v[r].z * inv, v[r].w * inv);
        uint2 u;
        u.x = *reinterpret_cast<uint32_t*>(&h0);
        u.y = *reinterpret_cast<uint32_t*>(&h1);
        ((uint2*)(g_pnh + (size_t)row * D))[lane] = u;
        if (lane == 0) g_rowsum[row] = 0.0f;
    }
}

// ---------------------------------------------------------------------------
// 2) Fused fp16 HMMA (fp16 accum) sim-GEMM + exp + row/col sums.
//    256 threads = 8 warps (2x4), warp tile 64x32, 3 CTAs/SM, cp.async loads.
// ---------------------------------------------------------------------------
__device__ __forceinline__ void ldsm4(uint32_t& r0, uint32_t& r1,
                                      uint32_t& r2, uint32_t& r3, uint32_t addr) {
    asm volatile("ldmatrix.sync.aligned.m8n8.x4.shared.b16 {%0,%1,%2,%3}, [%4];"
                 : "=r"(r0), "=r"(r1), "=r"(r2), "=r"(r3) : "r"(addr));
}
__device__ __forceinline__ void mma16816h(uint32_t* d, const uint32_t* a, const uint32_t* b) {
    asm volatile(
        "mma.sync.aligned.m16n8k16.row.col.f16.f16.f16.f16 "
        "{%0,%1}, {%2,%3,%4,%5}, {%6,%7}, {%0,%1};"
        : "+r"(d[0]), "+r"(d[1])
        : "r"(a[0]), "r"(a[1]), "r"(a[2]), "r"(a[3]), "r"(b[0]), "r"(b[1]));
}
__device__ __forceinline__ void cp16(uint32_t smem_addr, const void* gptr) {
    asm volatile("cp.async.cg.shared.global [%0], [%1], 16;"
                 :: "r"(smem_addr), "l"(gptr));
}

__global__ __launch_bounds__(256, 3) void simgemm_kernel() {
    // triangular decode: bid -> (by, bx <= by)
    int bid = blockIdx.x;
    int by = (int)((sqrtf(8.0f * (float)bid + 1.0f) - 1.0f) * 0.5f);
    while ((by + 1) * (by + 2) / 2 <= bid) by++;
    while (by * (by + 1) / 2 > bid) by--;
    int bx = bid - by * (by + 1) / 2;
    bool diag = (bx == by);

    extern __shared__ char smem_raw[];
    __half* As = (__half*)smem_raw;                          // [128][PITCH]
    __half* Bs = As + BM * PITCH;                            // [128][PITCH]
    float* rsum = (float*)(Bs + BM * PITCH);                 // [128]
    float* csum = rsum + BM;                                 // [128]

    int tid = threadIdx.x, lane = tid & 31, wid = tid >> 5;

    // ---- async tile loads (16B per thread per iter); diag reuses As as Bs
    const __half* srcA = g_pnh + (size_t)by * BM * D;
    const __half* srcB = g_pnh + (size_t)bx * BM * D;
    uint32_t aS = (uint32_t)__cvta_generic_to_shared(As);
    uint32_t bS = (uint32_t)__cvta_generic_to_shared(Bs);
#pragma unroll
    for (int it = 0; it < (BM * D) / (256 * 8); it++) {
        int e = it * 2048 + tid * 8;
        int row = e >> 7, col = e & 127;
        uint32_t off = (uint32_t)(row * PITCH + col) * 2u;
        cp16(aS + off, srcA + e);
        if (!diag) cp16(bS + off, srcB + e);
    }
    asm volatile("cp.async.commit_group;");
    if (tid < BM) { rsum[tid] = 0.0f; csum[tid] = 0.0f; }
    asm volatile("cp.async.wait_group 0;");
    __syncthreads();

    // ---- warp tiling: 2 (M) x 4 (N) warps; warp tile 64x32
    int wm = (wid >> 2) * 64;
    int wn = (wid & 3) * 32;
    uint32_t aTile = aS;
    uint32_t bTile = diag ? aS : bS;

    uint32_t acc[4][4][2];
#pragma unroll
    for (int mt = 0; mt < 4; mt++)
#pragma unroll
        for (int nt = 0; nt < 4; nt++) { acc[mt][nt][0] = 0u; acc[mt][nt][1] = 0u; }

#pragma unroll
    for (int ks = 0; ks < 8; ks++) {
        int k0 = ks * 16;
        uint32_t a[4][4], b[4][2];
#pragma unroll
        for (int mt = 0; mt < 4; mt++) {
            int row = wm + mt * 16 + (lane & 15);
            int col = k0 + ((lane >> 4) << 3);
            ldsm4(a[mt][0], a[mt][1], a[mt][2], a[mt][3],
                  aTile + (uint32_t)(row * PITCH + col) * 2u);
        }
#pragma unroll
        for (int np = 0; np < 2; np++) {
            int g = lane >> 3;
            int row = wn + np * 16 + ((g >> 1) << 3) + (lane & 7);
            int col = k0 + ((g & 1) << 3);
            uint32_t r0, r1, r2, r3;
            ldsm4(r0, r1, r2, r3, bTile + (uint32_t)(row * PITCH + col) * 2u);
            b[np * 2 + 0][0] = r0; b[np * 2 + 0][1] = r1;
            b[np * 2 + 1][0] = r2; b[np * 2 + 1][1] = r3;
        }
#pragma unroll
        for (int mt = 0; mt < 4; mt++)
#pragma unroll
            for (int nt = 0; nt < 4; nt++)
                mma16816h(acc[mt][nt], a[mt], b[nt]);
    }

    // ---- epilogue: unpack fp16 -> fp32, exp (sim <= 2), diag masked
    int r0 = lane >> 2, c0 = (lane & 3) * 2;
    float rp[8], cp[8];
#pragma unroll
    for (int i = 0; i < 8; i++) { rp[i] = 0.0f; cp[i] = 0.0f; }

#pragma unroll
    for (int mt = 0; mt < 4; mt++) {
#pragma unroll
        for (int nt = 0; nt < 4; nt++) {
            float2 p0 = __half22float2(*reinterpret_cast<__half2*>(&acc[mt][nt][0]));
            float2 p1 = __half22float2(*reinterpret_cast<__half2*>(&acc[mt][nt][1]));
            float e0 = __expf(p0.x * 2.0f);
            float e1 = __expf(p0.y * 2.0f);
            float e2 = __expf(p1.x * 2.0f);
            float e3 = __expf(p1.y * 2.0f);
            if (diag) {
                int lr = wm + mt * 16 + r0;
                int lc = wn + nt * 8 + c0;
                if (lr == lc)         e0 = 0.0f;
                if (lr == lc + 1)     e1 = 0.0f;
                if (lr + 8 == lc)     e2 = 0.0f;
                if (lr + 8 == lc + 1) e3 = 0.0f;
            }
            rp[mt * 2 + 0] += e0 + e1;
            rp[mt * 2 + 1] += e2 + e3;
            cp[nt * 2 + 0] += e0 + e2;
            cp[nt * 2 + 1] += e1 + e3;
        }
    }

#pragma unroll
    for (int o = 1; o <= 2; o <<= 1)
#pragma unroll
        for (int i = 0; i < 8; i++) rp[i] += __shfl_xor_sync(0xffffffffu, rp[i], o);
    if ((lane & 3) == 0) {
#pragma unroll
        for (int mt = 0; mt < 4; mt++) {
            atomicAdd(&rsum[wm + mt * 16 + r0 + 0], rp[mt * 2 + 0]);
            atomicAdd(&rsum[wm + mt * 16 + r0 + 8], rp[mt * 2 + 1]);
        }
    }
#pragma unroll
    for (int o = 4; o <= 16; o <<= 1)
#pragma unroll
        for (int i = 0; i < 8; i++) cp[i] += __shfl_xor_sync(0xffffffffu, cp[i], o);
    if (lane < 4) {
#pragma unroll
        for (int nt = 0; nt < 4; nt++) {
            atomicAdd(&csum[wn + nt * 8 + lane * 2 + 0], cp[nt * 2 + 0]);
            atomicAdd(&csum[wn + nt * 8 + lane * 2 + 1], cp[nt * 2 + 1]);
        }
    }
    __syncthreads();

    if (tid < BM) {
        atomicAdd(&g_rowsum[by * BM + tid], rsum[tid]);
    } else if (!diag) {
        atomicAdd(&g_rowsum[bx * BM + (tid - BM)], csum[tid - BM]);
    }
}

// ---------------------------------------------------------------------------
// 3) Finalize: 4 rows per warp; pos from fp16 rows (fp32 accumulate).
// ---------------------------------------------------------------------------
__global__ void finalize_kernel(float* __restrict__ out) {
    __shared__ float bred[8];
    int warp = (blockIdx.x * blockDim.x + threadIdx.x) >> 5;  // 0..2047
    int lane = threadIdx.x & 31, wib = (threadIdx.x >> 5);
    int row0 = warp * 4;

    float local = 0.0f;
    if (row0 < TN) {
        uint2 v[4], w[4];
#pragma unroll
        for (int r = 0; r < 4; r++) {
            int row = row0 + r;
            int pair = (row < NHALF) ? row + NHALF : row - NHALF;
            v[r] = ((const uint2*)(g_pnh + (size_t)row * D))[lane];
            w[r] = ((const uint2*)(g_pnh + (size_t)pair * D))[lane];
        }
#pragma unroll
        for (int r = 0; r < 4; r++) {
            float2 v0 = __half22float2(*reinterpret_cast<__half2*>(&v[r].x));
            float2 v1 = __half22float2(*reinterpret_cast<__half2*>(&v[r].y));
            float2 w0 = __half22float2(*reinterpret_cast<__half2*>(&w[r].x));
            float2 w1 = __half22float2(*reinterpret_cast<__half2*>(&w[r].y));
            float pd = v0.x * w0.x + v0.y * w0.y + v1.x * w1.x + v1.y * w1.y;
#pragma unroll
            for (int o = 16; o > 0; o >>= 1) pd += __shfl_xor_sync(0xffffffffu, pd, o);
            if (lane == 0)
                local += logf(g_rowsum[row0 + r]) - pd * 2.0f;
        }
    }
    if (lane == 0) bred[wib] = local;
    __syncthreads();
    if (threadIdx.x == 0) {
        float s = 0.0f;
#pragma unroll
        for (int i = 0; i < 8; i++) s += bred[i];
        atomicAdd(out, s * (1.0f / (float)TN));
    }
}

// ---------------------------------------------------------------------------
extern "C" void kernel_launch(void* const* d_in, const int* in_sizes, int n_in,
                              void* d_out, int out_size) {
    const float* zi = (const float*)d_in[0];
    const float* zj = (const float*)d_in[1];
    float* out = (float*)d_out;

    normalize_kernel<<<TN / 16, 256>>>(zi, zj, out);   // 512 blocks, also zeros out

    size_t smem_bytes = (size_t)(2 * BM * PITCH) * sizeof(__half)
                        + 2 * BM * sizeof(float);
    static bool attr_set = false;
    if (!attr_set) {
        cudaFuncSetAttribute(simgemm_kernel,
                             cudaFuncAttributeMaxDynamicSharedMemorySize,
                             (int)smem_bytes);
        attr_set = true;
    }
    simgemm_kernel<<<NTILES, 256, smem_bytes>>>();

    finalize_kernel<<<TN / 32, 256>>>(out);
}